// round 12
// baseline (speedup 1.0000x reference)
#include <cuda_runtime.h>

#define N_NODES 50000
#define N_EDGES 800000
#define IN_CH   64
#define HC      128      // HEADS * OUT_CH
#define HEADS   4
#define PAD     64       // per-node edge-slot capacity (P(deg>=64) ~ 2e-18/node)
#define NEG_SLOPE 0.2f
#define BN_EPS  1e-5f

#define GEMM_BLOCKS (N_NODES / 16)   // 3125
#define ZERO_BLOCKS 196

typedef unsigned long long ull;

// ---------------- static device scratch ----------------
__device__ float  g_xl[N_NODES * HC];        // 25.6 MB
__device__ float  g_xr[N_NODES * HC];        // 25.6 MB
__device__ int    g_cursor[N_NODES];         // per-node edge count (0 on entry)
__device__ float4 g_rec[N_NODES * PAD];      // {srcHC_bits, dx, dy, dz} 51.2 MB
__device__ float  g_attr_sum[3];
__device__ float  g_chansum[HC];
__device__ float  g_chansq[HC];

// ---------------- f32x2 helpers ----------------
__device__ __forceinline__ ull pk2(float a, float b) {
    ull r; asm("mov.b64 %0,{%1,%2};" : "=l"(r) : "f"(a), "f"(b)); return r;
}
__device__ __forceinline__ ull fma2(ull a, ull b, ull c) {
    ull d; asm("fma.rn.f32x2 %0,%1,%2,%3;" : "=l"(d) : "l"(a), "l"(b), "l"(c)); return d;
}
__device__ __forceinline__ ull add2(ull a, ull b) {
    ull d; asm("add.rn.f32x2 %0,%1,%2;" : "=l"(d) : "l"(a), "l"(b)); return d;
}
__device__ __forceinline__ ull mul2(ull a, ull b) {
    ull d; asm("mul.rn.f32x2 %0,%1,%2;" : "=l"(d) : "l"(a), "l"(b)); return d;
}
__device__ __forceinline__ ull abs2(ull a) {
    ull d; asm("and.b64 %0,%1,0x7FFFFFFF7FFFFFFF;" : "=l"(d) : "l"(a)); return d;
}
__device__ __forceinline__ void upk2(ull v, float& lo, float& hi) {
    asm("mov.b64 {%0,%1},%2;" : "=f"(lo), "=f"(hi) : "l"(v));
}

// ---------------- K1: fused GEMM (xl=x@Wl, xr=x@Wr) + zero per-run state -----
__global__ void __launch_bounds__(128) k_gemm(const float* __restrict__ x,
                                              const float* __restrict__ Wl,
                                              const float* __restrict__ Wr) {
    if (blockIdx.x >= GEMM_BLOCKS) {
        int zi = (blockIdx.x - GEMM_BLOCKS) * 128 + threadIdx.x;   // < 25088
        int i0 = zi * 2, i1 = zi * 2 + 1;
        if (i0 < N_NODES) g_cursor[i0] = 0;
        if (i1 < N_NODES) g_cursor[i1] = 0;
        if (zi < HC) { g_chansum[zi] = 0.f; g_chansq[zi] = 0.f; }
        if (zi < 3)  g_attr_sum[zi] = 0.f;
        return;
    }
    __shared__ float2 xsp[8][IN_CH];   // [node-pair][k] = {x[2p][k], x[2p+1][k]}
    int nb = blockIdx.x * 16;
    int t  = threadIdx.x;
    for (int idx = t; idx < 16 * IN_CH; idx += 128) {
        int n = idx >> 6, k = idx & 63;
        float v = x[(nb + n) * IN_CH + k];
        if (n & 1) xsp[n >> 1][k].y = v; else xsp[n >> 1][k].x = v;
    }
    __syncthreads();

    const float* W   = (t < 64) ? Wl : Wr;
    float*       dst = (t < 64) ? g_xl : g_xr;
    int c0 = t & 63;
    int c1 = c0 + 64;

    ull acc[8][2];
#pragma unroll
    for (int p = 0; p < 8; p++) { acc[p][0] = 0ull; acc[p][1] = 0ull; }

#pragma unroll 4
    for (int k = 0; k < IN_CH; k++) {
        float w0 = W[k * HC + c0];
        float w1 = W[k * HC + c1];
        ull wv0 = pk2(w0, w0);
        ull wv1 = pk2(w1, w1);
#pragma unroll
        for (int p = 0; p < 8; p++) {
            ull xp = *(const ull*)&xsp[p][k];
            acc[p][0] = fma2(xp, wv0, acc[p][0]);
            acc[p][1] = fma2(xp, wv1, acc[p][1]);
        }
    }
#pragma unroll
    for (int p = 0; p < 8; p++) {
        float lo, hi;
        upk2(acc[p][0], lo, hi);
        dst[(nb + 2 * p + 0) * HC + c0] = lo;
        dst[(nb + 2 * p + 1) * HC + c0] = hi;
        upk2(acc[p][1], lo, hi);
        dst[(nb + 2 * p + 0) * HC + c1] = lo;
        dst[(nb + 2 * p + 1) * HC + c1] = hi;
    }
}

// ---------------- K2: scatter edges into padded per-dst slots + attr sum -----
// rec.x holds s*HC (pre-scaled) so the aggregate gather needs no shift.
__global__ void k_scatter(const int* __restrict__ ei_raw,
                          const float* __restrict__ pos) {
    __shared__ int is64;
    if (threadIdx.x == 0) {
        // int64 LE values < 2^31 -> all odd 32-bit words zero
        int z = 1;
        for (int j = 1; j < 256; j += 2)
            if (ei_raw[j] != 0) { z = 0; break; }
        is64 = z;
    }
    __syncthreads();
    float s0 = 0.f, s1 = 0.f, s2 = 0.f;
    int stride = gridDim.x * blockDim.x;
    const int2* e2 = (const int2*)ei_raw;
    for (int e = blockIdx.x * blockDim.x + threadIdx.x; e < N_EDGES; e += stride) {
        int s, d;
        if (is64) { s = e2[e].x;   d = e2[N_EDGES + e].x; }
        else      { s = ei_raw[e]; d = ei_raw[N_EDGES + e]; }
        int p = atomicAdd(&g_cursor[d], 1);
        float4 r;
        r.x = __int_as_float(s * HC);
        r.y = pos[s * 3 + 0] - pos[d * 3 + 0];
        r.z = pos[s * 3 + 1] - pos[d * 3 + 1];
        r.w = pos[s * 3 + 2] - pos[d * 3 + 2];
        g_rec[d * PAD + p] = r;
        s0 += r.y; s1 += r.z; s2 += r.w;
    }
#pragma unroll
    for (int m = 16; m; m >>= 1) {
        s0 += __shfl_xor_sync(0xffffffffu, s0, m);
        s1 += __shfl_xor_sync(0xffffffffu, s1, m);
        s2 += __shfl_xor_sync(0xffffffffu, s2, m);
    }
    __shared__ float red[3][8];
    int wp = threadIdx.x >> 5, l = threadIdx.x & 31;
    if (l == 0) { red[0][wp] = s0; red[1][wp] = s1; red[2][wp] = s2; }
    __syncthreads();
    if (threadIdx.x < 3) {
        float acc = 0.f;
        for (int j = 0; j < 8; j++) acc += red[threadIdx.x][j];
        atomicAdd(&g_attr_sum[threadIdx.x], acc);
    }
}

// ---------------- K3: per-node GATv2 softmax + aggregation + stats -----------
// One warp per destination node; lane -> 4 consecutive channels (head=lane>>3).
// Full batches of 4 (no clamp/kill) + scalar tail; packed f32x2 score math
// with leaky-dot identity:
//   att . leaky(e) = 0.6*(att.e) + 0.4*(att.|e|)   (exact for slope 0.2)
__device__ __forceinline__ float edge_score_pk(
        ull xl01, ull xl23, ull xr01, ull xr23,
        float d0, float d1, float d2,
        ull we0a, ull we0b, ull we1a, ull we1b, ull we2a, ull we2b,
        ull at01, ull at23) {
    ull d0v = pk2(d0, d0), d1v = pk2(d1, d1), d2v = pk2(d2, d2);
    ull e01 = fma2(d0v, we0a, xr01);
    e01 = fma2(d1v, we1a, e01);
    e01 = fma2(d2v, we2a, e01);
    e01 = add2(e01, xl01);
    ull e23 = fma2(d0v, we0b, xr23);
    e23 = fma2(d1v, we1b, e23);
    e23 = fma2(d2v, we2b, e23);
    e23 = add2(e23, xl23);
    ull sA = mul2(at01, e01);        sA = fma2(at23, e23, sA);
    ull sB = mul2(at01, abs2(e01));  sB = fma2(at23, abs2(e23), sB);
    float al, ah, bl, bh;
    upk2(sA, al, ah);
    upk2(sB, bl, bh);
    return 0.6f * (al + ah) + 0.4f * (bl + bh);
}

__global__ void __launch_bounds__(256, 4) k_aggregate(
        const float* __restrict__ W_edge,
        const float* __restrict__ att,
        float* __restrict__ out) {
    __shared__ float ssum[HC], ssq[HC];
    if (threadIdx.x < HC) { ssum[threadIdx.x] = 0.f; ssq[threadIdx.x] = 0.f; }
    __syncthreads();

    int i    = (blockIdx.x * blockDim.x + threadIdx.x) >> 5;  // node id (exact grid)
    int lane = threadIdx.x & 31;
    int c4   = lane * 4;
    const float* xlb = g_xl + c4;     // per-lane base; offset = s*HC from rec

    ulonglong2 xrv = *(const ulonglong2*)(g_xr + i * HC + c4);
    ulonglong2 atv = *(const ulonglong2*)(att + c4);
    ulonglong2 w0v = *(const ulonglong2*)(W_edge + 0 * HC + c4);
    ulonglong2 w1v = *(const ulonglong2*)(W_edge + 1 * HC + c4);
    ulonglong2 w2v = *(const ulonglong2*)(W_edge + 2 * HC + c4);
    ull xr01 = xrv.x, xr23 = xrv.y;
    ull at01 = atv.x, at23 = atv.y;
    ull we0a = w0v.x, we0b = w0v.y;
    ull we1a = w1v.x, we1b = w1v.y;
    ull we2a = w2v.x, we2b = w2v.y;

    const float invE = 1.0f / (float)N_EDGES;
    float m0 = g_attr_sum[0] * invE;
    float m1 = g_attr_sum[1] * invE;
    float m2 = g_attr_sum[2] * invE;

    ull acc01 = 0ull, acc23 = 0ull;
    float denom = 0.f;

    int deg  = g_cursor[i];
    int full = deg & ~3;
    const float4* recp = g_rec + i * PAD;

    // ---- full batches of 4: no clamp, no kill ----
    for (int base = 0; base < full; base += 4) {
        float4 rec[4];
        ull x01[4], x23[4];
#pragma unroll
        for (int k = 0; k < 4; k++)
            rec[k] = recp[base + k];
#pragma unroll
        for (int k = 0; k < 4; k++) {
            ulonglong2 xv = *(const ulonglong2*)(xlb + __float_as_int(rec[k].x));
            x01[k] = xv.x;
            x23[k] = xv.y;
        }
#pragma unroll
        for (int k = 0; k < 4; k++) {
            float p = edge_score_pk(x01[k], x23[k], xr01, xr23,
                                    rec[k].y, rec[k].z, rec[k].w,
                                    we0a, we0b, we1a, we1b, we2a, we2b,
                                    at01, at23);
            p += __shfl_xor_sync(0xffffffffu, p, 1);
            p += __shfl_xor_sync(0xffffffffu, p, 2);
            p += __shfl_xor_sync(0xffffffffu, p, 4);
            float w = __expf(p);               // scores O(1): no max-subtraction
            denom += w;
            ull wv = pk2(w, w);
            acc01 = fma2(wv, x01[k], acc01);
            acc23 = fma2(wv, x23[k], acc23);
        }
    }
    // ---- tail edges (0..3) + self-loop, scalar path ----
    for (int e = full; e <= deg; e++) {
        float4 rec;
        if (e < deg) {
            rec = recp[e];
        } else {
            rec = make_float4(__int_as_float(i * HC), m0, m1, m2);  // self-loop
        }
        ulonglong2 xv = *(const ulonglong2*)(xlb + __float_as_int(rec.x));
        float p = edge_score_pk(xv.x, xv.y, xr01, xr23, rec.y, rec.z, rec.w,
                                we0a, we0b, we1a, we1b, we2a, we2b, at01, at23);
        p += __shfl_xor_sync(0xffffffffu, p, 1);
        p += __shfl_xor_sync(0xffffffffu, p, 2);
        p += __shfl_xor_sync(0xffffffffu, p, 4);
        float w = __expf(p);
        denom += w;
        ull wv = pk2(w, w);
        acc01 = fma2(wv, xv.x, acc01);
        acc23 = fma2(wv, xv.y, acc23);
    }

    float a0, a1, a2, a3;
    upk2(acc01, a0, a1);
    upk2(acc23, a2, a3);
    float inv = 1.f / (denom + 1e-16f);
    float4 o = make_float4(a0 * inv, a1 * inv, a2 * inv, a3 * inv);
    *(float4*)(out + i * HC + c4) = o;

    atomicAdd(&ssum[c4 + 0], o.x);  atomicAdd(&ssq[c4 + 0], o.x * o.x);
    atomicAdd(&ssum[c4 + 1], o.y);  atomicAdd(&ssq[c4 + 1], o.y * o.y);
    atomicAdd(&ssum[c4 + 2], o.z);  atomicAdd(&ssq[c4 + 2], o.z * o.z);
    atomicAdd(&ssum[c4 + 3], o.w);  atomicAdd(&ssq[c4 + 3], o.w * o.w);
    __syncthreads();
    if (threadIdx.x < HC) {
        atomicAdd(&g_chansum[threadIdx.x], ssum[threadIdx.x]);
        atomicAdd(&g_chansq[threadIdx.x],  ssq[threadIdx.x]);
    }
}

// ---------------- K4: BatchNorm — smem-cached scale/bias + pure streaming ----
__global__ void __launch_bounds__(256) k_bn(float* __restrict__ out,
                                            const float* __restrict__ gamma,
                                            const float* __restrict__ beta) {
    __shared__ float sscale[HC], sbias[HC];
    int t = threadIdx.x;
    if (t < HC) {
        const float invN = 1.0f / (float)N_NODES;
        float mu  = g_chansum[t] * invN;
        float var = g_chansq[t] * invN - mu * mu;
        float sc  = rsqrtf(var + BN_EPS) * gamma[t];
        sscale[t] = sc;
        sbias[t]  = beta[t] - mu * sc;
    }
    __syncthreads();
    int base = blockIdx.x * 512 + t;     // float4 index; 2 per thread
#pragma unroll
    for (int j = 0; j < 2; j++) {
        int idx = base + j * 256;        // < 1.6M exactly (3125*512)
        int c4  = (idx & 31) * 4;
        float4 v  = ((float4*)out)[idx];
        float4 sc = *(const float4*)&sscale[c4];
        float4 bi = *(const float4*)&sbias[c4];
        v.x = v.x * sc.x + bi.x;
        v.y = v.y * sc.y + bi.y;
        v.z = v.z * sc.z + bi.z;
        v.w = v.w * sc.w + bi.w;
        ((float4*)out)[idx] = v;
    }
}

// ---------------- launch ----------------
extern "C" void kernel_launch(void* const* d_in, const int* in_sizes, int n_in,
                              void* d_out, int out_size) {
    const float* x     = (const float*)d_in[0];
    const float* pos   = (const float*)d_in[1];
    const int*   eiraw = (const int*)d_in[2];
    const float* Wl    = (const float*)d_in[3];
    const float* Wr    = (const float*)d_in[4];
    const float* We    = (const float*)d_in[5];
    const float* att   = (const float*)d_in[6];
    const float* gamma = (const float*)d_in[7];
    const float* beta  = (const float*)d_in[8];
    float* out = (float*)d_out;

    k_gemm<<<GEMM_BLOCKS + ZERO_BLOCKS, 128>>>(x, Wl, Wr);
    k_scatter<<<592, 256>>>(eiraw, pos);
    k_aggregate<<<N_NODES / 8, 256>>>(We, att, out);
    k_bn<<<3125, 256>>>(out, gamma, beta);
}

// round 14
// speedup vs baseline: 1.0266x; 1.0266x over previous
#include <cuda_runtime.h>

#define N_NODES 50000
#define N_EDGES 800000
#define IN_CH   64
#define HC      128      // HEADS * OUT_CH
#define HEADS   4
#define PAD     64       // per-node edge-slot capacity (P(deg>=64) ~ 2e-18/node)
#define NEG_SLOPE 0.2f
#define BN_EPS  1e-5f
#define LOG2E   1.4426950408889634f

#define GEMM_BLOCKS (N_NODES / 16)   // 3125
#define ZERO_BLOCKS 196

typedef unsigned long long ull;

// ---------------- static device scratch ----------------
__device__ float  g_xl[N_NODES * HC];        // 25.6 MB
__device__ float  g_xr[N_NODES * HC];        // 25.6 MB
__device__ int    g_cursor[N_NODES];         // per-node edge count (0 on entry)
__device__ float4 g_rec[N_NODES * PAD];      // {srcHC_bits, dx, dy, dz} 51.2 MB
__device__ float4 g_pos4[N_NODES];           // padded positions, 800 KB
__device__ float  g_attr_sum[3];
__device__ float  g_chansum[HC];
__device__ float  g_chansq[HC];

// ---------------- f32x2 / exp2 helpers ----------------
__device__ __forceinline__ ull pk2(float a, float b) {
    ull r; asm("mov.b64 %0,{%1,%2};" : "=l"(r) : "f"(a), "f"(b)); return r;
}
__device__ __forceinline__ ull fma2(ull a, ull b, ull c) {
    ull d; asm("fma.rn.f32x2 %0,%1,%2,%3;" : "=l"(d) : "l"(a), "l"(b), "l"(c)); return d;
}
__device__ __forceinline__ ull add2(ull a, ull b) {
    ull d; asm("add.rn.f32x2 %0,%1,%2;" : "=l"(d) : "l"(a), "l"(b)); return d;
}
__device__ __forceinline__ ull mul2(ull a, ull b) {
    ull d; asm("mul.rn.f32x2 %0,%1,%2;" : "=l"(d) : "l"(a), "l"(b)); return d;
}
__device__ __forceinline__ ull abs2(ull a) {
    ull d; asm("and.b64 %0,%1,0x7FFFFFFF7FFFFFFF;" : "=l"(d) : "l"(a)); return d;
}
__device__ __forceinline__ void upk2(ull v, float& lo, float& hi) {
    asm("mov.b64 {%0,%1},%2;" : "=f"(lo), "=f"(hi) : "l"(v));
}
__device__ __forceinline__ float ex2(float x) {
    float r; asm("ex2.approx.f32 %0, %1;" : "=f"(r) : "f"(x)); return r;
}

// ---------------- K1: fused GEMM + zero state + pos4 staging -----------------
__global__ void __launch_bounds__(128) k_gemm(const float* __restrict__ x,
                                              const float* __restrict__ Wl,
                                              const float* __restrict__ Wr,
                                              const float* __restrict__ pos) {
    if (blockIdx.x >= GEMM_BLOCKS) {
        int zi = (blockIdx.x - GEMM_BLOCKS) * 128 + threadIdx.x;   // < 25088
        int i0 = zi * 2, i1 = zi * 2 + 1;
        if (i0 < N_NODES) {
            g_cursor[i0] = 0;
            g_pos4[i0] = make_float4(pos[i0*3], pos[i0*3+1], pos[i0*3+2], 0.f);
        }
        if (i1 < N_NODES) {
            g_cursor[i1] = 0;
            g_pos4[i1] = make_float4(pos[i1*3], pos[i1*3+1], pos[i1*3+2], 0.f);
        }
        if (zi < HC) { g_chansum[zi] = 0.f; g_chansq[zi] = 0.f; }
        if (zi < 3)  g_attr_sum[zi] = 0.f;
        return;
    }
    __shared__ float2 xsp[8][IN_CH];   // [node-pair][k] = {x[2p][k], x[2p+1][k]}
    int nb = blockIdx.x * 16;
    int t  = threadIdx.x;
    for (int idx = t; idx < 16 * IN_CH; idx += 128) {
        int n = idx >> 6, k = idx & 63;
        float v = x[(nb + n) * IN_CH + k];
        if (n & 1) xsp[n >> 1][k].y = v; else xsp[n >> 1][k].x = v;
    }
    __syncthreads();

    const float* W   = (t < 64) ? Wl : Wr;
    float*       dst = (t < 64) ? g_xl : g_xr;
    int c0 = t & 63;
    int c1 = c0 + 64;

    ull acc[8][2];
#pragma unroll
    for (int p = 0; p < 8; p++) { acc[p][0] = 0ull; acc[p][1] = 0ull; }

#pragma unroll 4
    for (int k = 0; k < IN_CH; k++) {
        float w0 = W[k * HC + c0];
        float w1 = W[k * HC + c1];
        ull wv0 = pk2(w0, w0);
        ull wv1 = pk2(w1, w1);
#pragma unroll
        for (int p = 0; p < 8; p++) {
            ull xp = *(const ull*)&xsp[p][k];
            acc[p][0] = fma2(xp, wv0, acc[p][0]);
            acc[p][1] = fma2(xp, wv1, acc[p][1]);
        }
    }
#pragma unroll
    for (int p = 0; p < 8; p++) {
        float lo, hi;
        upk2(acc[p][0], lo, hi);
        dst[(nb + 2 * p + 0) * HC + c0] = lo;
        dst[(nb + 2 * p + 1) * HC + c0] = hi;
        upk2(acc[p][1], lo, hi);
        dst[(nb + 2 * p + 0) * HC + c1] = lo;
        dst[(nb + 2 * p + 1) * HC + c1] = hi;
    }
}

// ---------------- K2: scatter edges into padded per-dst slots + attr sum -----
// rec.x holds s*HC (pre-scaled); pos gathers are single LDG.128 via g_pos4.
__global__ void k_scatter(const int* __restrict__ ei_raw) {
    __shared__ int is64;
    if (threadIdx.x == 0) {
        // int64 LE values < 2^31 -> all odd 32-bit words zero
        int z = 1;
        for (int j = 1; j < 256; j += 2)
            if (ei_raw[j] != 0) { z = 0; break; }
        is64 = z;
    }
    __syncthreads();
    float s0 = 0.f, s1 = 0.f, s2 = 0.f;
    int stride = gridDim.x * blockDim.x;
    const int2* e2 = (const int2*)ei_raw;
    for (int e = blockIdx.x * blockDim.x + threadIdx.x; e < N_EDGES; e += stride) {
        int s, d;
        if (is64) { s = e2[e].x;   d = e2[N_EDGES + e].x; }
        else      { s = ei_raw[e]; d = ei_raw[N_EDGES + e]; }
        int p = atomicAdd(&g_cursor[d], 1);
        float4 ps = g_pos4[s];
        float4 pd = g_pos4[d];
        float4 r;
        r.x = __int_as_float(s * HC);
        r.y = ps.x - pd.x;
        r.z = ps.y - pd.y;
        r.w = ps.z - pd.z;
        g_rec[d * PAD + p] = r;
        s0 += r.y; s1 += r.z; s2 += r.w;
    }
#pragma unroll
    for (int m = 16; m; m >>= 1) {
        s0 += __shfl_xor_sync(0xffffffffu, s0, m);
        s1 += __shfl_xor_sync(0xffffffffu, s1, m);
        s2 += __shfl_xor_sync(0xffffffffu, s2, m);
    }
    __shared__ float red[3][8];
    int wp = threadIdx.x >> 5, l = threadIdx.x & 31;
    if (l == 0) { red[0][wp] = s0; red[1][wp] = s1; red[2][wp] = s2; }
    __syncthreads();
    if (threadIdx.x < 3) {
        float acc = 0.f;
        for (int j = 0; j < 8; j++) acc += red[threadIdx.x][j];
        atomicAdd(&g_attr_sum[threadIdx.x], acc);
    }
}

// ---------------- K3: per-node GATv2 softmax + aggregation + stats -----------
// One warp per destination node; lane -> 4 consecutive channels (head=lane>>3).
// Batch=4 with clamp (proven shape); per-edge 3-shfl reduce + 1 ex2;
// leaky-dot identity with log2(e) folded into the blend constants:
//   log2e * att.leaky(e) = (0.6*log2e)*(att.e) + (0.4*log2e)*(att.|e|)
__device__ __forceinline__ float edge_score_pk(
        ull xl01, ull xl23, ull xr01, ull xr23,
        float d0, float d1, float d2,
        ull we0a, ull we0b, ull we1a, ull we1b, ull we2a, ull we2b,
        ull at01, ull at23) {
    ull d0v = pk2(d0, d0), d1v = pk2(d1, d1), d2v = pk2(d2, d2);
    ull e01 = fma2(d0v, we0a, xr01);
    e01 = fma2(d1v, we1a, e01);
    e01 = fma2(d2v, we2a, e01);
    e01 = add2(e01, xl01);
    ull e23 = fma2(d0v, we0b, xr23);
    e23 = fma2(d1v, we1b, e23);
    e23 = fma2(d2v, we2b, e23);
    e23 = add2(e23, xl23);
    ull sA = mul2(at01, e01);        sA = fma2(at23, e23, sA);
    ull sB = mul2(at01, abs2(e01));  sB = fma2(at23, abs2(e23), sB);
    float al, ah, bl, bh;
    upk2(sA, al, ah);
    upk2(sB, bl, bh);
    return (0.6f * LOG2E) * (al + ah) + (0.4f * LOG2E) * (bl + bh);
}

__global__ void __launch_bounds__(256, 4) k_aggregate(
        const float* __restrict__ W_edge,
        const float* __restrict__ att,
        float* __restrict__ out) {
    __shared__ float ssum[HC], ssq[HC];
    if (threadIdx.x < HC) { ssum[threadIdx.x] = 0.f; ssq[threadIdx.x] = 0.f; }
    __syncthreads();

    int i    = (blockIdx.x * blockDim.x + threadIdx.x) >> 5;  // node id (exact grid)
    int lane = threadIdx.x & 31;
    int c4   = lane * 4;
    const float* xlb = g_xl + c4;     // per-lane base; offset = s*HC from rec

    ulonglong2 xrv = *(const ulonglong2*)(g_xr + i * HC + c4);
    ulonglong2 atv = *(const ulonglong2*)(att + c4);
    ulonglong2 w0v = *(const ulonglong2*)(W_edge + 0 * HC + c4);
    ulonglong2 w1v = *(const ulonglong2*)(W_edge + 1 * HC + c4);
    ulonglong2 w2v = *(const ulonglong2*)(W_edge + 2 * HC + c4);
    ull xr01 = xrv.x, xr23 = xrv.y;
    ull at01 = atv.x, at23 = atv.y;
    ull we0a = w0v.x, we0b = w0v.y;
    ull we1a = w1v.x, we1b = w1v.y;
    ull we2a = w2v.x, we2b = w2v.y;

    const float invE = 1.0f / (float)N_EDGES;
    float m0 = g_attr_sum[0] * invE;
    float m1 = g_attr_sum[1] * invE;
    float m2 = g_attr_sum[2] * invE;

    ull acc01 = 0ull, acc23 = 0ull;
    float denom = 0.f;

    int deg = g_cursor[i];
    const float4* recp = g_rec + i * PAD;
    for (int base = 0; base < deg; base += 4) {
        int m = deg - base;
        float4 rec[4];
        ull x01[4], x23[4];
#pragma unroll
        for (int k = 0; k < 4; k++)
            rec[k] = recp[min(base + k, deg - 1)];   // clamp: pad killed via p below
#pragma unroll
        for (int k = 0; k < 4; k++) {
            ulonglong2 xv = *(const ulonglong2*)(xlb + __float_as_int(rec[k].x));
            x01[k] = xv.x;
            x23[k] = xv.y;
        }
#pragma unroll
        for (int k = 0; k < 4; k++) {
            float p = edge_score_pk(x01[k], x23[k], xr01, xr23,
                                    rec[k].y, rec[k].z, rec[k].w,
                                    we0a, we0b, we1a, we1b, we2a, we2b,
                                    at01, at23);
            p += __shfl_xor_sync(0xffffffffu, p, 1);
            p += __shfl_xor_sync(0xffffffffu, p, 2);
            p += __shfl_xor_sync(0xffffffffu, p, 4);
            if (k >= m) p = -1e30f;            // padded (clamped) edge -> weight 0
            float w = ex2(p);                  // log2e pre-folded; scores O(1)
            denom += w;
            ull wv = pk2(w, w);
            acc01 = fma2(wv, x01[k], acc01);
            acc23 = fma2(wv, x23[k], acc23);
        }
    }
    // self-loop with mean edge_attr
    {
        ulonglong2 xv = *(const ulonglong2*)(xlb + i * HC);
        float p = edge_score_pk(xv.x, xv.y, xr01, xr23, m0, m1, m2,
                                we0a, we0b, we1a, we1b, we2a, we2b, at01, at23);
        p += __shfl_xor_sync(0xffffffffu, p, 1);
        p += __shfl_xor_sync(0xffffffffu, p, 2);
        p += __shfl_xor_sync(0xffffffffu, p, 4);
        float w = ex2(p);
        denom += w;
        ull wv = pk2(w, w);
        acc01 = fma2(wv, xv.x, acc01);
        acc23 = fma2(wv, xv.y, acc23);
    }

    float a0, a1, a2, a3;
    upk2(acc01, a0, a1);
    upk2(acc23, a2, a3);
    float inv = 1.f / (denom + 1e-16f);
    float4 o = make_float4(a0 * inv, a1 * inv, a2 * inv, a3 * inv);
    *(float4*)(out + i * HC + c4) = o;

    atomicAdd(&ssum[c4 + 0], o.x);  atomicAdd(&ssq[c4 + 0], o.x * o.x);
    atomicAdd(&ssum[c4 + 1], o.y);  atomicAdd(&ssq[c4 + 1], o.y * o.y);
    atomicAdd(&ssum[c4 + 2], o.z);  atomicAdd(&ssq[c4 + 2], o.z * o.z);
    atomicAdd(&ssum[c4 + 3], o.w);  atomicAdd(&ssq[c4 + 3], o.w * o.w);
    __syncthreads();
    if (threadIdx.x < HC) {
        atomicAdd(&g_chansum[threadIdx.x], ssum[threadIdx.x]);
        atomicAdd(&g_chansq[threadIdx.x],  ssq[threadIdx.x]);
    }
}

// ---------------- K4: BatchNorm — smem scale/bias, 4 float4/thread for MLP ---
__global__ void __launch_bounds__(256) k_bn(float* __restrict__ out,
                                            const float* __restrict__ gamma,
                                            const float* __restrict__ beta) {
    __shared__ float sscale[HC], sbias[HC];
    int t = threadIdx.x;
    if (t < HC) {
        const float invN = 1.0f / (float)N_NODES;
        float mu  = g_chansum[t] * invN;
        float var = g_chansq[t] * invN - mu * mu;
        float sc  = rsqrtf(var + BN_EPS) * gamma[t];
        sscale[t] = sc;
        sbias[t]  = beta[t] - mu * sc;
    }
    __syncthreads();
    int base = blockIdx.x * 1024 + t;    // float4 index; 4 per thread
    float4 v[4];
    int idx[4];
#pragma unroll
    for (int j = 0; j < 4; j++) {
        idx[j] = base + j * 256;
        if (idx[j] < N_NODES * HC / 4) v[j] = ((float4*)out)[idx[j]];
    }
#pragma unroll
    for (int j = 0; j < 4; j++) {
        if (idx[j] < N_NODES * HC / 4) {
            int c4 = (idx[j] & 31) * 4;
            float4 sc = *(const float4*)&sscale[c4];
            float4 bi = *(const float4*)&sbias[c4];
            v[j].x = v[j].x * sc.x + bi.x;
            v[j].y = v[j].y * sc.y + bi.y;
            v[j].z = v[j].z * sc.z + bi.z;
            v[j].w = v[j].w * sc.w + bi.w;
            ((float4*)out)[idx[j]] = v[j];
        }
    }
}

// ---------------- launch ----------------
extern "C" void kernel_launch(void* const* d_in, const int* in_sizes, int n_in,
                              void* d_out, int out_size) {
    const float* x     = (const float*)d_in[0];
    const float* pos   = (const float*)d_in[1];
    const int*   eiraw = (const int*)d_in[2];
    const float* Wl    = (const float*)d_in[3];
    const float* Wr    = (const float*)d_in[4];
    const float* We    = (const float*)d_in[5];
    const float* att   = (const float*)d_in[6];
    const float* gamma = (const float*)d_in[7];
    const float* beta  = (const float*)d_in[8];
    float* out = (float*)d_out;

    k_gemm<<<GEMM_BLOCKS + ZERO_BLOCKS, 128>>>(x, Wl, Wr, pos);
    k_scatter<<<592, 256>>>(eiraw);
    k_aggregate<<<N_NODES / 8, 256>>>(We, att, out);
    k_bn<<<1563, 256>>>(out, gamma, beta);
}